// round 15
// baseline (speedup 1.0000x reference)
#include <cuda_runtime.h>
#include <cuda_fp16.h>
#include <math.h>
#include <stdint.h>

#define B_  4
#define LQ_ 5440
#define D_  256
#define H_  8
#define HD_ 32
#define FF_ 1024
#define NL_ 6
#define MROWS (B_*LQ_)   // 21760

// ---------------- scratch (device globals; no allocation) ----------------
__device__ float  g_pos  [MROWS*D_];
__device__ float  g_out  [MROWS*D_];
__device__ __half g_out16[MROWS*D_];
__device__ __half g_qpos16[MROWS*D_];
__device__ float  g_oa   [MROWS*384];
__device__ __half g_vh   [MROWS*256];
__device__ __half g_def16[MROWS*D_];
__device__ __half g_ffn16[MROWS*FF_];
__device__ __half g_wh_voa[NL_*640*256];
__device__ __half g_wh_o  [NL_*256*256];
__device__ __half g_wh_f1 [NL_*1024*256];
__device__ __half g_wh_f2 [NL_*256*1024];
__device__ float  g_bc    [NL_*640];

// ---------------- fused flatten ----------------
__global__ void flatten_all_kernel(
    const float* __restrict__ s0, const float* __restrict__ s1,
    const float* __restrict__ s2, const float* __restrict__ s3,
    const float* __restrict__ p0, const float* __restrict__ p1,
    const float* __restrict__ p2, const float* __restrict__ p3,
    const float* __restrict__ lvl_emb,
    float* __restrict__ dsrc, float* __restrict__ dpos,
    __half* __restrict__ dsrc16, __half* __restrict__ dqpos16)
{
    __shared__ float ts[32][33];
    __shared__ float tp[32][33];

    int t = blockIdx.x;
    int level, hwt, HW, base;
    if      (t < 128) { level = 0; hwt = t;       HW = 4096; base = 0;    }
    else if (t < 160) { level = 1; hwt = t - 128; HW = 1024; base = 4096; }
    else if (t < 168) { level = 2; hwt = t - 160; HW = 256;  base = 5120; }
    else              { level = 3; hwt = t - 168; HW = 64;   base = 5376; }

    const float* src = (level == 0) ? s0 : (level == 1) ? s1 : (level == 2) ? s2 : s3;
    const float* pos = (level == 0) ? p0 : (level == 1) ? p1 : (level == 2) ? p2 : p3;

    int b  = blockIdx.z;
    int tx = threadIdx.x, ty = threadIdx.y;
    int hw0 = hwt * 32;
    int d0  = blockIdx.y * 32;

    const float* sp = src + ((size_t)b * D_) * HW;
    const float* pp = pos + ((size_t)b * D_) * HW;
    #pragma unroll
    for (int j = 0; j < 32; j += 8) {
        ts[ty + j][tx] = sp[(size_t)(d0 + ty + j) * HW + hw0 + tx];
        tp[ty + j][tx] = pp[(size_t)(d0 + ty + j) * HW + hw0 + tx];
    }
    __syncthreads();
    float add = lvl_emb[level * D_ + d0 + tx];
    #pragma unroll
    for (int j = 0; j < 32; j += 8) {
        int hw = hw0 + ty + j;
        size_t row = ((size_t)b * LQ_ + base + hw) * D_ + d0 + tx;
        float sv = ts[tx][ty + j];
        float pv = tp[tx][ty + j] + add;
        dsrc[row]    = sv;
        dpos[row]    = pv;
        dsrc16[row]  = __float2half(sv);
        dqpos16[row] = __float2half(sv + pv);
    }
}

// ---------------- fused weight transpose (f32 [K,N] -> f16 [N,K]) + bias ----------
__global__ void wtrans_all_kernel(
    const float* __restrict__ Wv,  const float* __restrict__ Woff,
    const float* __restrict__ Wattn, const float* __restrict__ Wo,
    const float* __restrict__ Wf1, const float* __restrict__ Wf2,
    const float* __restrict__ bv, const float* __restrict__ boff,
    const float* __restrict__ battn,
    __half* __restrict__ wvoa, __half* __restrict__ wo,
    __half* __restrict__ wf1, __half* __restrict__ wf2,
    float* __restrict__ bc)
{
    __shared__ float t[32][33];
    int tl = blockIdx.x, l = blockIdx.z;
    int tid = threadIdx.y * 32 + threadIdx.x;

    if (tl == 736) {
        for (int n = tid; n < 640; n += 256) {
            float v;
            if      (n < 256) v = bv  [l * 256 + n];
            else if (n < 512) v = boff[l * 256 + (n - 256)];
            else              v = battn[l * 128 + (n - 512)];
            bc[l * 640 + n] = v;
        }
        return;
    }

    const float* src; __half* dst; int K, N, idx;
    if      (tl < 64)  { src=Wv   +(size_t)l*65536;  dst=wvoa+(size_t)l*163840;          K=256;  N=256;  idx=tl;       }
    else if (tl < 128) { src=Woff +(size_t)l*65536;  dst=wvoa+(size_t)l*163840+65536;    K=256;  N=256;  idx=tl-64;    }
    else if (tl < 160) { src=Wattn+(size_t)l*32768;  dst=wvoa+(size_t)l*163840+131072;   K=256;  N=128;  idx=tl-128;   }
    else if (tl < 224) { src=Wo   +(size_t)l*65536;  dst=wo  +(size_t)l*65536;           K=256;  N=256;  idx=tl-160;   }
    else if (tl < 480) { src=Wf1  +(size_t)l*262144; dst=wf1 +(size_t)l*262144;          K=256;  N=1024; idx=tl-224;   }
    else               { src=Wf2  +(size_t)l*262144; dst=wf2 +(size_t)l*262144;          K=1024; N=256;  idx=tl-480;   }
    int ntn = N >> 5;
    int n0 = (idx % ntn) * 32;
    int k0 = (idx / ntn) * 32;
    int tx = threadIdx.x, ty = threadIdx.y;
    #pragma unroll
    for (int j = 0; j < 32; j += 8)
        t[ty + j][tx] = src[(size_t)(k0 + ty + j) * N + n0 + tx];
    __syncthreads();
    #pragma unroll
    for (int j = 0; j < 32; j += 8)
        dst[(size_t)(n0 + ty + j) * K + k0 + tx] = __float2half(t[tx][ty + j]);
}

// ---------------- asm helpers ----------------
__device__ __forceinline__ void mma_f16(float* d, const uint32_t* a, const uint32_t* b)
{
    asm volatile("mma.sync.aligned.m16n8k16.row.col.f32.f16.f16.f32 "
        "{%0,%1,%2,%3}, {%4,%5,%6,%7}, {%8,%9}, {%0,%1,%2,%3};"
        : "+f"(d[0]), "+f"(d[1]), "+f"(d[2]), "+f"(d[3])
        : "r"(a[0]), "r"(a[1]), "r"(a[2]), "r"(a[3]), "r"(b[0]), "r"(b[1]));
}
__device__ __forceinline__ void ldsm4(uint32_t* r, uint32_t addr)
{
    asm volatile("ldmatrix.sync.aligned.m8n8.x4.shared.b16 {%0,%1,%2,%3}, [%4];"
        : "=r"(r[0]), "=r"(r[1]), "=r"(r[2]), "=r"(r[3]) : "r"(addr));
}
__device__ __forceinline__ void cpa16(uint32_t dst, const void* src)
{
    asm volatile("cp.async.cg.shared.global [%0], [%1], 16;" :: "r"(dst), "l"(src));
}
#define CP_COMMIT() asm volatile("cp.async.commit_group;" ::: "memory")
#define CP_WAIT2()  asm volatile("cp.async.wait_group 2;" ::: "memory")

// ================= fp16 GEMM A: BM=128 BN=128 BK=32 (VOA, FC1) ==================
#define STG_BYTES 20480
#define GEMM_SMEM (4*STG_BYTES)
template<int DO_RELU, int MODE>
__global__ void __launch_bounds__(256, 2) tgemm16_kernel(
    const __half* __restrict__ A0, const __half* __restrict__ A1,
    const __half* __restrict__ Wt, const float* __restrict__ bias,
    float* __restrict__ C, __half* __restrict__ C16,
    int N, int K, int bn_split)
{
    extern __shared__ char smc[];
    uint32_t smb = (uint32_t)__cvta_generic_to_shared(smc);

    int tid  = threadIdx.x;
    int lane = tid & 31;
    int wrp  = tid >> 5;
    int g    = lane >> 2;
    int tg   = lane & 3;

    int bm = blockIdx.y * 128;
    int bn = blockIdx.x * 128;
    int wm = (wrp >> 2) * 64;
    int wn = (wrp & 3) * 32;

    const __half* A = ((int)blockIdx.x < bn_split) ? A0 : A1;

    int r0l = (tid + 0)   >> 2, c0l = (tid + 0)   & 3;
    int r1l = (tid + 256) >> 2, c1l = (tid + 256) & 3;
    const __half* gA0 = A  + (size_t)(bm + r0l) * K + c0l * 8;
    const __half* gA1 = A  + (size_t)(bm + r1l) * K + c1l * 8;
    const __half* gB0 = Wt + (size_t)(bn + r0l) * K + c0l * 8;
    const __half* gB1 = Wt + (size_t)(bn + r1l) * K + c1l * 8;
    uint32_t dA0 = r0l * 80 + c0l * 16;
    uint32_t dA1 = r1l * 80 + c1l * 16;

    uint32_t a_off = (uint32_t)((lane & 15) * 80 + ((lane & 16) ? 16 : 0));
    uint32_t b_off = (uint32_t)(((lane & 7) + ((lane & 16) ? 8 : 0)) * 80 + ((lane & 8) ? 16 : 0));

    float acc[4][4][4];
    #pragma unroll
    for (int i = 0; i < 4; i++)
        #pragma unroll
        for (int j = 0; j < 4; j++)
            #pragma unroll
            for (int r = 0; r < 4; r++) acc[i][j][r] = 0.0f;

    int NIT = K >> 5;

    #pragma unroll
    for (int s = 0; s < 3; s++) {
        int k0 = s << 5;
        uint32_t sb = smb + s * STG_BYTES;
        cpa16(sb + dA0,         gA0 + k0);
        cpa16(sb + dA1,         gA1 + k0);
        cpa16(sb + 10240 + dA0, gB0 + k0);
        cpa16(sb + 10240 + dA1, gB1 + k0);
        CP_COMMIT();
    }

    for (int it = 0; it < NIT; it++) {
        CP_WAIT2();
        __syncthreads();

        if (it + 3 < NIT) {
            int s = (it + 3) & 3;
            int k0 = (it + 3) << 5;
            uint32_t sb = smb + s * STG_BYTES;
            cpa16(sb + dA0,         gA0 + k0);
            cpa16(sb + dA1,         gA1 + k0);
            cpa16(sb + 10240 + dA0, gB0 + k0);
            cpa16(sb + 10240 + dA1, gB1 + k0);
        }
        CP_COMMIT();

        uint32_t sb = smb + (it & 3) * STG_BYTES;
        uint32_t abase = sb + wm * 80 + a_off;
        uint32_t bbase = sb + 10240 + wn * 80 + b_off;

        #pragma unroll
        for (int ksg = 0; ksg < 2; ksg++) {
            uint32_t a[4][4];
            #pragma unroll
            for (int mt = 0; mt < 4; mt++)
                ldsm4(a[mt], abase + mt * 16 * 80 + ksg * 32);
            uint32_t b[4][2];
            #pragma unroll
            for (int ntp = 0; ntp < 2; ntp++) {
                uint32_t r[4];
                ldsm4(r, bbase + ntp * 16 * 80 + ksg * 32);
                b[2 * ntp + 0][0] = r[0]; b[2 * ntp + 0][1] = r[1];
                b[2 * ntp + 1][0] = r[2]; b[2 * ntp + 1][1] = r[3];
            }
            #pragma unroll
            for (int mt = 0; mt < 4; mt++)
                #pragma unroll
                for (int nt = 0; nt < 4; nt++)
                    mma_f16(acc[mt][nt], a[mt], b[nt]);
        }
    }

    bool v16 = (MODE == 1) && ((int)blockIdx.x < bn_split);
    #pragma unroll
    for (int nt = 0; nt < 4; nt++) {
        int n = bn + wn + nt * 8 + 2 * tg;
        float b0 = bias[n], b1 = bias[n + 1];
        #pragma unroll
        for (int mt = 0; mt < 4; mt++) {
            int m0 = bm + wm + mt * 16 + g;
            float l0 = acc[mt][nt][0] + b0, l1 = acc[mt][nt][1] + b1;
            float h0 = acc[mt][nt][2] + b0, h1 = acc[mt][nt][3] + b1;
            if (DO_RELU) {
                l0 = fmaxf(l0, 0.f); l1 = fmaxf(l1, 0.f);
                h0 = fmaxf(h0, 0.f); h1 = fmaxf(h1, 0.f);
            }
            if (MODE == 1) {
                if (v16) {
                    *(__half2*)(C16 + (size_t)m0 * 256 + n)       = __floats2half2_rn(l0, l1);
                    *(__half2*)(C16 + (size_t)(m0 + 8) * 256 + n) = __floats2half2_rn(h0, h1);
                } else {
                    int nc = n - 256;
                    float2 lo = {l0, l1}, hi = {h0, h1};
                    *(float2*)(C + (size_t)m0 * 384 + nc)       = lo;
                    *(float2*)(C + (size_t)(m0 + 8) * 384 + nc) = hi;
                }
            } else {
                *(__half2*)(C16 + (size_t)m0 * N + n)       = __floats2half2_rn(l0, l1);
                *(__half2*)(C16 + (size_t)(m0 + 8) * N + n) = __floats2half2_rn(h0, h1);
            }
        }
    }
}

// ========== fp16 GEMM B: BM=32 BN=256, LN-fused epilogue (O-proj, FC2) ==========
// 8 warps, each 32 rows x 32 cols. Stage: A 32*80 + B 256*80 = 23040 B.
#define LSTG_BYTES 23040
#define LGEMM_SMEM (4*LSTG_BYTES)
__global__ void __launch_bounds__(256, 2) tgemm16_ln_kernel(
    const __half* __restrict__ A, const __half* __restrict__ Wt,
    const float* __restrict__ bias, const float* __restrict__ X,
    const float* __restrict__ gma, const float* __restrict__ bta,
    float* __restrict__ OUT, __half* __restrict__ OUT16,
    const float* __restrict__ pos, __half* __restrict__ qpos16, int K)
{
    extern __shared__ char smc[];
    uint32_t smb = (uint32_t)__cvta_generic_to_shared(smc);
    __shared__ float red[32][8][2];

    int tid  = threadIdx.x;
    int lane = tid & 31;
    int wrp  = tid >> 5;
    int g    = lane >> 2;
    int tg   = lane & 3;

    int bm = blockIdx.x * 32;
    int wn = wrp * 32;

    // A loader: first 128 threads, 1 chunk each (32 rows x 4 chunks)
    int ra = tid >> 2, ca = tid & 3;
    const __half* gA = A + (size_t)(bm + ra) * K + ca * 8;
    uint32_t dA = ra * 80 + ca * 16;
    bool loadA = (tid < 128);
    // B loader: 4 chunks/thread (256 rows x 4 chunks)
    const __half* gB[4];
    uint32_t dB[4];
    #pragma unroll
    for (int j = 0; j < 4; j++) {
        int rb = (tid + 256 * j) >> 2, cb = (tid + 256 * j) & 3;
        gB[j] = Wt + (size_t)rb * K + cb * 8;
        dB[j] = 2560 + rb * 80 + cb * 16;
    }

    uint32_t a_off = (uint32_t)((lane & 15) * 80 + ((lane & 16) ? 16 : 0));
    uint32_t b_off = (uint32_t)(((lane & 7) + ((lane & 16) ? 8 : 0)) * 80 + ((lane & 8) ? 16 : 0));

    float acc[2][4][4];
    #pragma unroll
    for (int i = 0; i < 2; i++)
        #pragma unroll
        for (int j = 0; j < 4; j++)
            #pragma unroll
            for (int r = 0; r < 4; r++) acc[i][j][r] = 0.0f;

    int NIT = K >> 5;

    #pragma unroll
    for (int s = 0; s < 3; s++) {
        int k0 = s << 5;
        uint32_t sb = smb + s * LSTG_BYTES;
        if (loadA) cpa16(sb + dA, gA + k0);
        #pragma unroll
        for (int j = 0; j < 4; j++) cpa16(sb + dB[j], gB[j] + k0);
        CP_COMMIT();
    }

    for (int it = 0; it < NIT; it++) {
        CP_WAIT2();
        __syncthreads();

        if (it + 3 < NIT) {
            int s = (it + 3) & 3;
            int k0 = (it + 3) << 5;
            uint32_t sb = smb + s * LSTG_BYTES;
            if (loadA) cpa16(sb + dA, gA + k0);
            #pragma unroll
            for (int j = 0; j < 4; j++) cpa16(sb + dB[j], gB[j] + k0);
        }
        CP_COMMIT();

        uint32_t sb = smb + (it & 3) * LSTG_BYTES;
        uint32_t abase = sb + a_off;
        uint32_t bbase = sb + 2560 + wn * 80 + b_off;

        #pragma unroll
        for (int ksg = 0; ksg < 2; ksg++) {
            uint32_t a[2][4];
            #pragma unroll
            for (int mt = 0; mt < 2; mt++)
                ldsm4(a[mt], abase + mt * 16 * 80 + ksg * 32);
            uint32_t b[4][2];
            #pragma unroll
            for (int ntp = 0; ntp < 2; ntp++) {
                uint32_t r[4];
                ldsm4(r, bbase + ntp * 16 * 80 + ksg * 32);
                b[2 * ntp + 0][0] = r[0]; b[2 * ntp + 0][1] = r[1];
                b[2 * ntp + 1][0] = r[2]; b[2 * ntp + 1][1] = r[3];
            }
            #pragma unroll
            for (int mt = 0; mt < 2; mt++)
                #pragma unroll
                for (int nt = 0; nt < 4; nt++)
                    mma_f16(acc[mt][nt], a[mt], b[nt]);
        }
    }
    __syncthreads();

    // epilogue: v = acc + bias + X; LN over 256 cols (8 warps x 32 cols)
    float sum[2][2] = {{0, 0}, {0, 0}};
    float sq [2][2] = {{0, 0}, {0, 0}};
    #pragma unroll
    for (int mt = 0; mt < 2; mt++) {
        #pragma unroll
        for (int nt = 0; nt < 4; nt++) {
            int n = wn + nt * 8 + 2 * tg;
            float b0 = bias[n], b1 = bias[n + 1];
            int mA = bm + mt * 16 + g;
            float2 x0 = *(const float2*)(X + (size_t)mA * 256 + n);
            float2 x1 = *(const float2*)(X + (size_t)(mA + 8) * 256 + n);
            acc[mt][nt][0] += b0 + x0.x;
            acc[mt][nt][1] += b1 + x0.y;
            acc[mt][nt][2] += b0 + x1.x;
            acc[mt][nt][3] += b1 + x1.y;
            sum[mt][0] += acc[mt][nt][0] + acc[mt][nt][1];
            sum[mt][1] += acc[mt][nt][2] + acc[mt][nt][3];
            sq[mt][0]  += acc[mt][nt][0] * acc[mt][nt][0] + acc[mt][nt][1] * acc[mt][nt][1];
            sq[mt][1]  += acc[mt][nt][2] * acc[mt][nt][2] + acc[mt][nt][3] * acc[mt][nt][3];
        }
    }
    #pragma unroll
    for (int mt = 0; mt < 2; mt++)
        #pragma unroll
        for (int rr = 0; rr < 2; rr++) {
            #pragma unroll
            for (int o = 1; o < 4; o <<= 1) {
                sum[mt][rr] += __shfl_xor_sync(0xffffffffu, sum[mt][rr], o);
                sq [mt][rr] += __shfl_xor_sync(0xffffffffu, sq [mt][rr], o);
            }
        }
    if (tg == 0) {
        #pragma unroll
        for (int mt = 0; mt < 2; mt++)
            #pragma unroll
            for (int rr = 0; rr < 2; rr++) {
                int rl = mt * 16 + g + rr * 8;
                red[rl][wrp][0] = sum[mt][rr];
                red[rl][wrp][1] = sq[mt][rr];
            }
    }
    __syncthreads();

    #pragma unroll
    for (int mt = 0; mt < 2; mt++) {
        #pragma unroll
        for (int rr = 0; rr < 2; rr++) {
            int rl = mt * 16 + g + rr * 8;
            float s = 0.f, s2 = 0.f;
            #pragma unroll
            for (int w = 0; w < 8; w++) { s += red[rl][w][0]; s2 += red[rl][w][1]; }
            float mean = s * (1.0f / 256.0f);
            float var  = s2 * (1.0f / 256.0f) - mean * mean;
            float inv  = rsqrtf(var + 1e-5f);
            int m = bm + rl;
            #pragma unroll
            for (int nt = 0; nt < 4; nt++) {
                int n = wn + nt * 8 + 2 * tg;
                float g0 = gma[n], g1 = gma[n + 1];
                float t0 = bta[n], t1 = bta[n + 1];
                float v0 = acc[mt][nt][2 * rr + 0];
                float v1 = acc[mt][nt][2 * rr + 1];
                float o0 = (v0 - mean) * inv * g0 + t0;
                float o1 = (v1 - mean) * inv * g1 + t1;
                float2 ov = {o0, o1};
                *(float2*)(OUT + (size_t)m * 256 + n) = ov;
                if (OUT16)
                    *(__half2*)(OUT16 + (size_t)m * 256 + n) = __floats2half2_rn(o0, o1);
                if (qpos16) {
                    float2 pv = *(const float2*)(pos + (size_t)m * 256 + n);
                    *(__half2*)(qpos16 + (size_t)m * 256 + n) =
                        __floats2half2_rn(o0 + pv.x, o1 + pv.y);
                }
            }
        }
    }
}

// ---------------- deformable attention: 2 points/iteration, inline ref ----------------
__global__ void __launch_bounds__(256) deform_kernel(
    const __half* __restrict__ vh,
    const float* __restrict__ oa,
    __half* __restrict__ out16)
{
    int bq   = blockIdx.x;
    int h    = threadIdx.x >> 5;
    int lane = threadIdx.x & 31;
    int b = bq / LQ_;
    int q = bq % LQ_;

    // inline reference point (grid centers; level sizes are powers of 2)
    int qb, qs;
    if      (q < 4096) { qb = 0;    qs = 6; }
    else if (q < 5120) { qb = 4096; qs = 5; }
    else if (q < 5376) { qb = 5120; qs = 4; }
    else               { qb = 5376; qs = 3; }
    int idx = q - qb;
    int Wq  = 1 << qs;
    float invW = 1.0f / (float)Wq;
    float refx = ((idx & (Wq - 1)) + 0.5f) * invW;
    float refy = ((idx >> qs) + 0.5f) * invW;

    const float* lg = oa + (size_t)bq * 384 + 256 + h * 16;
    float xv = (lane < 16) ? lg[lane] : -1e30f;
    float m = xv;
    #pragma unroll
    for (int o = 8; o; o >>= 1) m = fmaxf(m, __shfl_xor_sync(0xffffffffu, m, o));
    float e = (lane < 16) ? __expf(xv - m) : 0.0f;
    float s = e;
    #pragma unroll
    for (int o = 8; o; o >>= 1) s += __shfl_xor_sync(0xffffffffu, s, o);
    float aw = e / s;

    float offv = oa[(size_t)bq * 384 + h * 32 + lane];

    int group  = lane >> 4;
    int corner = (lane >> 2) & 3;
    int cx = corner & 1;
    int cy = corner >> 1;
    int chunk  = lane & 3;

    const __half* vbase = vh + (size_t)b * LQ_ * 256 + h * HD_ + chunk * 8;

    float acc[8];
    #pragma unroll
    for (int j = 0; j < 8; j++) acc[j] = 0.0f;

    const int dims [4] = {64, 32, 16, 8};
    const int bases[4] = {0, 4096, 5120, 5376};

    #pragma unroll
    for (int l = 0; l < 4; l++) {
        const int Wl = dims[l];
        const int base = bases[l];
        const float Wf = (float)Wl;
        #pragma unroll
        for (int pp = 0; pp < 2; pp++) {
            int pt = l * 4 + pp * 2 + group;
            float ax = __shfl_sync(0xffffffffu, offv, pt * 2 + 0);
            float ay = __shfl_sync(0xffffffffu, offv, pt * 2 + 1);
            float a  = __shfl_sync(0xffffffffu, aw, pt);
            float xf = refx * Wf + ax - 0.5f;
            float yf = refy * Wf + ay - 0.5f;
            float x0f = floorf(xf), y0f = floorf(yf);
            float wx = xf - x0f, wy = yf - y0f;
            int xc = (int)x0f + cx;
            int yc = (int)y0f + cy;
            float wxt = cx ? wx : (1.f - wx);
            float wyt = cy ? wy : (1.f - wy);
            bool valid = (xc >= 0) & (xc < Wl) & (yc >= 0) & (yc < Wl);
            float w = valid ? (a * wxt * wyt) : 0.f;
            int xcc = min(max(xc, 0), Wl - 1);
            int ycc = min(max(yc, 0), Wl - 1);

            uint4 d = *(const uint4*)(vbase + (size_t)(base + ycc * Wl + xcc) * 256);
            const __half2* hp = (const __half2*)&d;
            #pragma unroll
            for (int j = 0; j < 4; j++) {
                float2 f = __half22float2(hp[j]);
                acc[2 * j + 0] = fmaf(w, f.x, acc[2 * j + 0]);
                acc[2 * j + 1] = fmaf(w, f.y, acc[2 * j + 1]);
            }
        }
    }

    #pragma unroll
    for (int o = 4; o <= 16; o <<= 1)
        #pragma unroll
        for (int j = 0; j < 8; j++)
            acc[j] += __shfl_xor_sync(0xffffffffu, acc[j], o);

    if (lane < 4) {
        __half2 p0 = __floats2half2_rn(acc[0], acc[1]);
        __half2 p1 = __floats2half2_rn(acc[2], acc[3]);
        __half2 p2 = __floats2half2_rn(acc[4], acc[5]);
        __half2 p3 = __floats2half2_rn(acc[6], acc[7]);
        uint4 pk = {*(uint32_t*)&p0, *(uint32_t*)&p1, *(uint32_t*)&p2, *(uint32_t*)&p3};
        *(uint4*)(out16 + (size_t)bq * 256 + h * HD_ + chunk * 8) = pk;
    }
}

// ---------------- host orchestration ----------------
static void* sym_ptr_raw(const void* sym)
{
    void* p = nullptr;
    cudaGetSymbolAddress(&p, sym);
    return p;
}

extern "C" void kernel_launch(void* const* d_in, const int* in_sizes, int n_in,
                              void* d_out, int out_size)
{
    bool interleaved = (in_sizes[1] == in_sizes[0]);
    const float* srcs[4];
    const float* poss[4];
    for (int l = 0; l < 4; l++) {
        srcs[l] = (const float*)d_in[interleaved ? 2 * l     : l];
        poss[l] = (const float*)d_in[interleaved ? 2 * l + 1 : 4 + l];
    }
    const float* level_embed = (const float*)d_in[8];
    const float* W_off  = (const float*)d_in[9];
    const float* b_off  = (const float*)d_in[10];
    const float* W_attn = (const float*)d_in[11];
    const float* b_attn = (const float*)d_in[12];
    const float* W_v    = (const float*)d_in[13];
    const float* b_v    = (const float*)d_in[14];
    const float* W_o    = (const float*)d_in[15];
    const float* b_o    = (const float*)d_in[16];
    const float* ln1_g  = (const float*)d_in[17];
    const float* ln1_b  = (const float*)d_in[18];
    const float* W_fc1  = (const float*)d_in[19];
    const float* b_fc1  = (const float*)d_in[20];
    const float* W_fc2  = (const float*)d_in[21];
    const float* b_fc2  = (const float*)d_in[22];
    const float* ln2_g  = (const float*)d_in[23];
    const float* ln2_b  = (const float*)d_in[24];

    float*  pos   = (float*) sym_ptr_raw(g_pos);
    float*  out   = (float*) sym_ptr_raw(g_out);
    __half* out16 = (__half*)sym_ptr_raw(g_out16);
    __half* qp16  = (__half*)sym_ptr_raw(g_qpos16);
    float*  oa    = (float*) sym_ptr_raw(g_oa);
    __half* vh    = (__half*)sym_ptr_raw(g_vh);
    __half* def16 = (__half*)sym_ptr_raw(g_def16);
    __half* ffn16 = (__half*)sym_ptr_raw(g_ffn16);
    __half* wvoa  = (__half*)sym_ptr_raw(g_wh_voa);
    __half* wo    = (__half*)sym_ptr_raw(g_wh_o);
    __half* wf1   = (__half*)sym_ptr_raw(g_wh_f1);
    __half* wf2   = (__half*)sym_ptr_raw(g_wh_f2);
    float*  bc    = (float*) sym_ptr_raw(g_bc);

    cudaFuncSetAttribute(tgemm16_kernel<0,1>, cudaFuncAttributeMaxDynamicSharedMemorySize, GEMM_SMEM);
    cudaFuncSetAttribute(tgemm16_kernel<1,2>, cudaFuncAttributeMaxDynamicSharedMemorySize, GEMM_SMEM);
    cudaFuncSetAttribute(tgemm16_ln_kernel, cudaFuncAttributeMaxDynamicSharedMemorySize, LGEMM_SMEM);

    dim3 tb(32, 8);
    flatten_all_kernel<<<dim3(170, D_ / 32, B_), tb>>>(
        srcs[0], srcs[1], srcs[2], srcs[3],
        poss[0], poss[1], poss[2], poss[3],
        level_embed, out, pos, out16, qp16);                               // 1
    wtrans_all_kernel<<<dim3(737, 1, NL_), tb>>>(W_v, W_off, W_attn, W_o, W_fc1, W_fc2,
                                                 b_v, b_off, b_attn,
                                                 wvoa, wo, wf1, wf2, bc);  // 2

    const int MB  = MROWS / 128; // 170
    const int LB2 = MROWS / 32;  // 680
    for (int i = 0; i < NL_; i++) {
        const __half* Wvoa = wvoa  + (size_t)i * 640 * 256;
        const float*  Bc   = bc    + (size_t)i * 640;
        const __half* Wo   = wo    + (size_t)i * 256 * 256;
        const float*  bo   = b_o   + (size_t)i * D_;
        const __half* Wf1  = wf1   + (size_t)i * 1024 * 256;
        const float*  bf1  = b_fc1 + (size_t)i * FF_;
        const __half* Wf2  = wf2   + (size_t)i * 256 * 1024;
        const float*  bf2  = b_fc2 + (size_t)i * D_;

        tgemm16_kernel<0,1><<<dim3(5, MB), 256, GEMM_SMEM>>>(
            out16, qp16, Wvoa, Bc, oa, vh, 640, 256, 2);                   // 3

        deform_kernel<<<MROWS, 256>>>(vh, oa, def16);                      // 4 <- profiled

        tgemm16_ln_kernel<<<LB2, 256, LGEMM_SMEM>>>(def16, Wo, bo, out,
            ln1_g + i * D_, ln1_b + i * D_, out, out16, nullptr, nullptr, 256);

        tgemm16_kernel<1,2><<<dim3(8, MB), 256, GEMM_SMEM>>>(
            out16, out16, Wf1, bf1, nullptr, ffn16, 1024, 256, 0);

        if (i == NL_ - 1) {
            tgemm16_ln_kernel<<<LB2, 256, LGEMM_SMEM>>>(ffn16, Wf2, bf2, out,
                ln2_g + i * D_, ln2_b + i * D_, (float*)d_out, nullptr, nullptr, nullptr, 1024);
        } else {
            tgemm16_ln_kernel<<<LB2, 256, LGEMM_SMEM>>>(ffn16, Wf2, bf2, out,
                ln2_g + i * D_, ln2_b + i * D_, out, out16, pos, qp16, 1024);
        }
    }
}

// round 16
// speedup vs baseline: 1.0521x; 1.0521x over previous
#include <cuda_runtime.h>
#include <cuda_fp16.h>
#include <math.h>
#include <stdint.h>

#define B_  4
#define LQ_ 5440
#define D_  256
#define H_  8
#define HD_ 32
#define FF_ 1024
#define NL_ 6
#define MROWS (B_*LQ_)   // 21760

// ---------------- scratch (device globals; no allocation) ----------------
__device__ float  g_pos  [MROWS*D_];
__device__ float  g_out  [MROWS*D_];
__device__ __half g_out16[MROWS*D_];
__device__ __half g_qpos16[MROWS*D_];
__device__ float  g_oa   [MROWS*384];
__device__ __half g_vh   [MROWS*256];
__device__ __half g_def16[MROWS*D_];
__device__ __half g_ffn16[MROWS*FF_];
__device__ __half g_wh_voa[NL_*640*256];
__device__ __half g_wh_o  [NL_*256*256];
__device__ __half g_wh_f1 [NL_*1024*256];
__device__ __half g_wh_f2 [NL_*256*1024];
__device__ float  g_bc    [NL_*640];

// ---------------- fused flatten ----------------
__global__ void flatten_all_kernel(
    const float* __restrict__ s0, const float* __restrict__ s1,
    const float* __restrict__ s2, const float* __restrict__ s3,
    const float* __restrict__ p0, const float* __restrict__ p1,
    const float* __restrict__ p2, const float* __restrict__ p3,
    const float* __restrict__ lvl_emb,
    float* __restrict__ dsrc, float* __restrict__ dpos,
    __half* __restrict__ dsrc16, __half* __restrict__ dqpos16)
{
    __shared__ float ts[32][33];
    __shared__ float tp[32][33];

    int t = blockIdx.x;
    int level, hwt, HW, base;
    if      (t < 128) { level = 0; hwt = t;       HW = 4096; base = 0;    }
    else if (t < 160) { level = 1; hwt = t - 128; HW = 1024; base = 4096; }
    else if (t < 168) { level = 2; hwt = t - 160; HW = 256;  base = 5120; }
    else              { level = 3; hwt = t - 168; HW = 64;   base = 5376; }

    const float* src = (level == 0) ? s0 : (level == 1) ? s1 : (level == 2) ? s2 : s3;
    const float* pos = (level == 0) ? p0 : (level == 1) ? p1 : (level == 2) ? p2 : p3;

    int b  = blockIdx.z;
    int tx = threadIdx.x, ty = threadIdx.y;
    int hw0 = hwt * 32;
    int d0  = blockIdx.y * 32;

    const float* sp = src + ((size_t)b * D_) * HW;
    const float* pp = pos + ((size_t)b * D_) * HW;
    #pragma unroll
    for (int j = 0; j < 32; j += 8) {
        ts[ty + j][tx] = sp[(size_t)(d0 + ty + j) * HW + hw0 + tx];
        tp[ty + j][tx] = pp[(size_t)(d0 + ty + j) * HW + hw0 + tx];
    }
    __syncthreads();
    float add = lvl_emb[level * D_ + d0 + tx];
    #pragma unroll
    for (int j = 0; j < 32; j += 8) {
        int hw = hw0 + ty + j;
        size_t row = ((size_t)b * LQ_ + base + hw) * D_ + d0 + tx;
        float sv = ts[tx][ty + j];
        float pv = tp[tx][ty + j] + add;
        dsrc[row]    = sv;
        dpos[row]    = pv;
        dsrc16[row]  = __float2half(sv);
        dqpos16[row] = __float2half(sv + pv);
    }
}

// ---------------- fused weight transpose (f32 [K,N] -> f16 [N,K]) + bias ----------
__global__ void wtrans_all_kernel(
    const float* __restrict__ Wv,  const float* __restrict__ Woff,
    const float* __restrict__ Wattn, const float* __restrict__ Wo,
    const float* __restrict__ Wf1, const float* __restrict__ Wf2,
    const float* __restrict__ bv, const float* __restrict__ boff,
    const float* __restrict__ battn,
    __half* __restrict__ wvoa, __half* __restrict__ wo,
    __half* __restrict__ wf1, __half* __restrict__ wf2,
    float* __restrict__ bc)
{
    __shared__ float t[32][33];
    int tl = blockIdx.x, l = blockIdx.z;
    int tid = threadIdx.y * 32 + threadIdx.x;

    if (tl == 736) {
        for (int n = tid; n < 640; n += 256) {
            float v;
            if      (n < 256) v = bv  [l * 256 + n];
            else if (n < 512) v = boff[l * 256 + (n - 256)];
            else              v = battn[l * 128 + (n - 512)];
            bc[l * 640 + n] = v;
        }
        return;
    }

    const float* src; __half* dst; int K, N, idx;
    if      (tl < 64)  { src=Wv   +(size_t)l*65536;  dst=wvoa+(size_t)l*163840;          K=256;  N=256;  idx=tl;       }
    else if (tl < 128) { src=Woff +(size_t)l*65536;  dst=wvoa+(size_t)l*163840+65536;    K=256;  N=256;  idx=tl-64;    }
    else if (tl < 160) { src=Wattn+(size_t)l*32768;  dst=wvoa+(size_t)l*163840+131072;   K=256;  N=128;  idx=tl-128;   }
    else if (tl < 224) { src=Wo   +(size_t)l*65536;  dst=wo  +(size_t)l*65536;           K=256;  N=256;  idx=tl-160;   }
    else if (tl < 480) { src=Wf1  +(size_t)l*262144; dst=wf1 +(size_t)l*262144;          K=256;  N=1024; idx=tl-224;   }
    else               { src=Wf2  +(size_t)l*262144; dst=wf2 +(size_t)l*262144;          K=1024; N=256;  idx=tl-480;   }
    int ntn = N >> 5;
    int n0 = (idx % ntn) * 32;
    int k0 = (idx / ntn) * 32;
    int tx = threadIdx.x, ty = threadIdx.y;
    #pragma unroll
    for (int j = 0; j < 32; j += 8)
        t[ty + j][tx] = src[(size_t)(k0 + ty + j) * N + n0 + tx];
    __syncthreads();
    #pragma unroll
    for (int j = 0; j < 32; j += 8)
        dst[(size_t)(n0 + ty + j) * K + k0 + tx] = __float2half(t[tx][ty + j]);
}

// ---------------- asm helpers ----------------
__device__ __forceinline__ void mma_f16(float* d, const uint32_t* a, const uint32_t* b)
{
    asm volatile("mma.sync.aligned.m16n8k16.row.col.f32.f16.f16.f32 "
        "{%0,%1,%2,%3}, {%4,%5,%6,%7}, {%8,%9}, {%0,%1,%2,%3};"
        : "+f"(d[0]), "+f"(d[1]), "+f"(d[2]), "+f"(d[3])
        : "r"(a[0]), "r"(a[1]), "r"(a[2]), "r"(a[3]), "r"(b[0]), "r"(b[1]));
}
__device__ __forceinline__ void ldsm4(uint32_t* r, uint32_t addr)
{
    asm volatile("ldmatrix.sync.aligned.m8n8.x4.shared.b16 {%0,%1,%2,%3}, [%4];"
        : "=r"(r[0]), "=r"(r[1]), "=r"(r[2]), "=r"(r[3]) : "r"(addr));
}
__device__ __forceinline__ void cpa16(uint32_t dst, const void* src)
{
    asm volatile("cp.async.cg.shared.global [%0], [%1], 16;" :: "r"(dst), "l"(src));
}
#define CP_COMMIT() asm volatile("cp.async.commit_group;" ::: "memory")
#define CP_WAIT2()  asm volatile("cp.async.wait_group 2;" ::: "memory")

// ================= fp16 GEMM A: BM=128 BN=128 BK=32 (VOA, FC1) ==================
#define STG_BYTES 20480
#define GEMM_SMEM (4*STG_BYTES)
template<int DO_RELU, int MODE>
__global__ void __launch_bounds__(256, 2) tgemm16_kernel(
    const __half* __restrict__ A0, const __half* __restrict__ A1,
    const __half* __restrict__ Wt, const float* __restrict__ bias,
    float* __restrict__ C, __half* __restrict__ C16,
    int N, int K, int bn_split)
{
    extern __shared__ char smc[];
    uint32_t smb = (uint32_t)__cvta_generic_to_shared(smc);

    int tid  = threadIdx.x;
    int lane = tid & 31;
    int wrp  = tid >> 5;
    int g    = lane >> 2;
    int tg   = lane & 3;

    int bm = blockIdx.y * 128;
    int bn = blockIdx.x * 128;
    int wm = (wrp >> 2) * 64;
    int wn = (wrp & 3) * 32;

    const __half* A = ((int)blockIdx.x < bn_split) ? A0 : A1;

    int r0l = (tid + 0)   >> 2, c0l = (tid + 0)   & 3;
    int r1l = (tid + 256) >> 2, c1l = (tid + 256) & 3;
    const __half* gA0 = A  + (size_t)(bm + r0l) * K + c0l * 8;
    const __half* gA1 = A  + (size_t)(bm + r1l) * K + c1l * 8;
    const __half* gB0 = Wt + (size_t)(bn + r0l) * K + c0l * 8;
    const __half* gB1 = Wt + (size_t)(bn + r1l) * K + c1l * 8;
    uint32_t dA0 = r0l * 80 + c0l * 16;
    uint32_t dA1 = r1l * 80 + c1l * 16;

    uint32_t a_off = (uint32_t)((lane & 15) * 80 + ((lane & 16) ? 16 : 0));
    uint32_t b_off = (uint32_t)(((lane & 7) + ((lane & 16) ? 8 : 0)) * 80 + ((lane & 8) ? 16 : 0));

    float acc[4][4][4];
    #pragma unroll
    for (int i = 0; i < 4; i++)
        #pragma unroll
        for (int j = 0; j < 4; j++)
            #pragma unroll
            for (int r = 0; r < 4; r++) acc[i][j][r] = 0.0f;

    int NIT = K >> 5;

    #pragma unroll
    for (int s = 0; s < 3; s++) {
        int k0 = s << 5;
        uint32_t sb = smb + s * STG_BYTES;
        cpa16(sb + dA0,         gA0 + k0);
        cpa16(sb + dA1,         gA1 + k0);
        cpa16(sb + 10240 + dA0, gB0 + k0);
        cpa16(sb + 10240 + dA1, gB1 + k0);
        CP_COMMIT();
    }

    for (int it = 0; it < NIT; it++) {
        CP_WAIT2();
        __syncthreads();

        if (it + 3 < NIT) {
            int s = (it + 3) & 3;
            int k0 = (it + 3) << 5;
            uint32_t sb = smb + s * STG_BYTES;
            cpa16(sb + dA0,         gA0 + k0);
            cpa16(sb + dA1,         gA1 + k0);
            cpa16(sb + 10240 + dA0, gB0 + k0);
            cpa16(sb + 10240 + dA1, gB1 + k0);
        }
        CP_COMMIT();

        uint32_t sb = smb + (it & 3) * STG_BYTES;
        uint32_t abase = sb + wm * 80 + a_off;
        uint32_t bbase = sb + 10240 + wn * 80 + b_off;

        #pragma unroll
        for (int ksg = 0; ksg < 2; ksg++) {
            uint32_t a[4][4];
            #pragma unroll
            for (int mt = 0; mt < 4; mt++)
                ldsm4(a[mt], abase + mt * 16 * 80 + ksg * 32);
            uint32_t b[4][2];
            #pragma unroll
            for (int ntp = 0; ntp < 2; ntp++) {
                uint32_t r[4];
                ldsm4(r, bbase + ntp * 16 * 80 + ksg * 32);
                b[2 * ntp + 0][0] = r[0]; b[2 * ntp + 0][1] = r[1];
                b[2 * ntp + 1][0] = r[2]; b[2 * ntp + 1][1] = r[3];
            }
            #pragma unroll
            for (int mt = 0; mt < 4; mt++)
                #pragma unroll
                for (int nt = 0; nt < 4; nt++)
                    mma_f16(acc[mt][nt], a[mt], b[nt]);
        }
    }

    bool v16 = (MODE == 1) && ((int)blockIdx.x < bn_split);
    #pragma unroll
    for (int nt = 0; nt < 4; nt++) {
        int n = bn + wn + nt * 8 + 2 * tg;
        float b0 = bias[n], b1 = bias[n + 1];
        #pragma unroll
        for (int mt = 0; mt < 4; mt++) {
            int m0 = bm + wm + mt * 16 + g;
            float l0 = acc[mt][nt][0] + b0, l1 = acc[mt][nt][1] + b1;
            float h0 = acc[mt][nt][2] + b0, h1 = acc[mt][nt][3] + b1;
            if (DO_RELU) {
                l0 = fmaxf(l0, 0.f); l1 = fmaxf(l1, 0.f);
                h0 = fmaxf(h0, 0.f); h1 = fmaxf(h1, 0.f);
            }
            if (MODE == 1) {
                if (v16) {
                    *(__half2*)(C16 + (size_t)m0 * 256 + n)       = __floats2half2_rn(l0, l1);
                    *(__half2*)(C16 + (size_t)(m0 + 8) * 256 + n) = __floats2half2_rn(h0, h1);
                } else {
                    int nc = n - 256;
                    float2 lo = {l0, l1}, hi = {h0, h1};
                    *(float2*)(C + (size_t)m0 * 384 + nc)       = lo;
                    *(float2*)(C + (size_t)(m0 + 8) * 384 + nc) = hi;
                }
            } else {
                *(__half2*)(C16 + (size_t)m0 * N + n)       = __floats2half2_rn(l0, l1);
                *(__half2*)(C16 + (size_t)(m0 + 8) * N + n) = __floats2half2_rn(h0, h1);
            }
        }
    }
}

// ========== fp16 GEMM B: BM=64 BN=256, LN-fused epilogue (O-proj, FC2) ==========
#define LSTG_BYTES 25600
#define LGEMM_SMEM (4*LSTG_BYTES)
__global__ void __launch_bounds__(256, 2) tgemm16_ln_kernel(
    const __half* __restrict__ A, const __half* __restrict__ Wt,
    const float* __restrict__ bias, const float* __restrict__ X,
    const float* __restrict__ gma, const float* __restrict__ bta,
    float* __restrict__ OUT, __half* __restrict__ OUT16,
    const float* __restrict__ pos, __half* __restrict__ qpos16, int K)
{
    extern __shared__ char smc[];
    uint32_t smb = (uint32_t)__cvta_generic_to_shared(smc);
    __shared__ float red[64][4][2];

    int tid  = threadIdx.x;
    int lane = tid & 31;
    int wrp  = tid >> 5;
    int g    = lane >> 2;
    int tg   = lane & 3;

    int bm = blockIdx.x * 64;
    int wml = (wrp >> 2) * 32;
    int wn  = (wrp & 3) * 64;

    int ra = tid >> 2, ca = tid & 3;
    const __half* gA = A + (size_t)(bm + ra) * K + ca * 8;
    uint32_t dA = ra * 80 + ca * 16;
    const __half* gB[4];
    uint32_t dB[4];
    #pragma unroll
    for (int j = 0; j < 4; j++) {
        int rb = (tid + 256 * j) >> 2, cb = (tid + 256 * j) & 3;
        gB[j] = Wt + (size_t)rb * K + cb * 8;
        dB[j] = 5120 + rb * 80 + cb * 16;
    }

    uint32_t a_off = (uint32_t)((lane & 15) * 80 + ((lane & 16) ? 16 : 0));
    uint32_t b_off = (uint32_t)(((lane & 7) + ((lane & 16) ? 8 : 0)) * 80 + ((lane & 8) ? 16 : 0));

    float acc[2][8][4];
    #pragma unroll
    for (int i = 0; i < 2; i++)
        #pragma unroll
        for (int j = 0; j < 8; j++)
            #pragma unroll
            for (int r = 0; r < 4; r++) acc[i][j][r] = 0.0f;

    int NIT = K >> 5;

    #pragma unroll
    for (int s = 0; s < 3; s++) {
        int k0 = s << 5;
        uint32_t sb = smb + s * LSTG_BYTES;
        cpa16(sb + dA, gA + k0);
        #pragma unroll
        for (int j = 0; j < 4; j++) cpa16(sb + dB[j], gB[j] + k0);
        CP_COMMIT();
    }

    for (int it = 0; it < NIT; it++) {
        CP_WAIT2();
        __syncthreads();

        if (it + 3 < NIT) {
            int s = (it + 3) & 3;
            int k0 = (it + 3) << 5;
            uint32_t sb = smb + s * LSTG_BYTES;
            cpa16(sb + dA, gA + k0);
            #pragma unroll
            for (int j = 0; j < 4; j++) cpa16(sb + dB[j], gB[j] + k0);
        }
        CP_COMMIT();

        uint32_t sb = smb + (it & 3) * LSTG_BYTES;
        uint32_t abase = sb + wml * 80 + a_off;
        uint32_t bbase = sb + 5120 + wn * 80 + b_off;

        #pragma unroll
        for (int ksg = 0; ksg < 2; ksg++) {
            uint32_t a[2][4];
            #pragma unroll
            for (int mt = 0; mt < 2; mt++)
                ldsm4(a[mt], abase + mt * 16 * 80 + ksg * 32);
            uint32_t b[8][2];
            #pragma unroll
            for (int ntp = 0; ntp < 4; ntp++) {
                uint32_t r[4];
                ldsm4(r, bbase + ntp * 16 * 80 + ksg * 32);
                b[2 * ntp + 0][0] = r[0]; b[2 * ntp + 0][1] = r[1];
                b[2 * ntp + 1][0] = r[2]; b[2 * ntp + 1][1] = r[3];
            }
            #pragma unroll
            for (int mt = 0; mt < 2; mt++)
                #pragma unroll
                for (int nt = 0; nt < 8; nt++)
                    mma_f16(acc[mt][nt], a[mt], b[nt]);
        }
    }
    __syncthreads();

    float sum[2][2] = {{0, 0}, {0, 0}};
    float sq [2][2] = {{0, 0}, {0, 0}};
    #pragma unroll
    for (int mt = 0; mt < 2; mt++) {
        #pragma unroll
        for (int nt = 0; nt < 8; nt++) {
            int n = wn + nt * 8 + 2 * tg;
            float b0 = bias[n], b1 = bias[n + 1];
            int mA = bm + wml + mt * 16 + g;
            float2 x0 = *(const float2*)(X + (size_t)mA * 256 + n);
            float2 x1 = *(const float2*)(X + (size_t)(mA + 8) * 256 + n);
            acc[mt][nt][0] += b0 + x0.x;
            acc[mt][nt][1] += b1 + x0.y;
            acc[mt][nt][2] += b0 + x1.x;
            acc[mt][nt][3] += b1 + x1.y;
            sum[mt][0] += acc[mt][nt][0] + acc[mt][nt][1];
            sum[mt][1] += acc[mt][nt][2] + acc[mt][nt][3];
            sq[mt][0]  += acc[mt][nt][0] * acc[mt][nt][0] + acc[mt][nt][1] * acc[mt][nt][1];
            sq[mt][1]  += acc[mt][nt][2] * acc[mt][nt][2] + acc[mt][nt][3] * acc[mt][nt][3];
        }
    }
    #pragma unroll
    for (int mt = 0; mt < 2; mt++)
        #pragma unroll
        for (int rr = 0; rr < 2; rr++) {
            #pragma unroll
            for (int o = 1; o < 4; o <<= 1) {
                sum[mt][rr] += __shfl_xor_sync(0xffffffffu, sum[mt][rr], o);
                sq [mt][rr] += __shfl_xor_sync(0xffffffffu, sq [mt][rr], o);
            }
        }
    int nw = wrp & 3;
    if (tg == 0) {
        #pragma unroll
        for (int mt = 0; mt < 2; mt++)
            #pragma unroll
            for (int rr = 0; rr < 2; rr++) {
                int rl = wml + mt * 16 + g + rr * 8;
                red[rl][nw][0] = sum[mt][rr];
                red[rl][nw][1] = sq[mt][rr];
            }
    }
    __syncthreads();

    #pragma unroll
    for (int mt = 0; mt < 2; mt++) {
        #pragma unroll
        for (int rr = 0; rr < 2; rr++) {
            int rl = wml + mt * 16 + g + rr * 8;
            float s  = red[rl][0][0] + red[rl][1][0] + red[rl][2][0] + red[rl][3][0];
            float s2 = red[rl][0][1] + red[rl][1][1] + red[rl][2][1] + red[rl][3][1];
            float mean = s * (1.0f / 256.0f);
            float var  = s2 * (1.0f / 256.0f) - mean * mean;
            float inv  = rsqrtf(var + 1e-5f);
            int m = bm + rl;
            #pragma unroll
            for (int nt = 0; nt < 8; nt++) {
                int n = wn + nt * 8 + 2 * tg;
                float g0 = gma[n], g1 = gma[n + 1];
                float t0 = bta[n], t1 = bta[n + 1];
                float v0 = acc[mt][nt][2 * rr + 0];
                float v1 = acc[mt][nt][2 * rr + 1];
                float o0 = (v0 - mean) * inv * g0 + t0;
                float o1 = (v1 - mean) * inv * g1 + t1;
                float2 ov = {o0, o1};
                *(float2*)(OUT + (size_t)m * 256 + n) = ov;
                if (OUT16)
                    *(__half2*)(OUT16 + (size_t)m * 256 + n) = __floats2half2_rn(o0, o1);
                if (qpos16) {
                    float2 pv = *(const float2*)(pos + (size_t)m * 256 + n);
                    *(__half2*)(qpos16 + (size_t)m * 256 + n) =
                        __floats2half2_rn(o0 + pv.x, o1 + pv.y);
                }
            }
        }
    }
}

// ---------------- deformable attention: 2 pts/iter, inline ref, wrap clamp ----------------
__global__ void __launch_bounds__(256) deform_kernel(
    const __half* __restrict__ vh,
    const float* __restrict__ oa,
    __half* __restrict__ out16)
{
    int bq   = blockIdx.x;
    int h    = threadIdx.x >> 5;
    int lane = threadIdx.x & 31;
    int b = bq / LQ_;
    int q = bq % LQ_;

    int qb, qs;
    if      (q < 4096) { qb = 0;    qs = 6; }
    else if (q < 5120) { qb = 4096; qs = 5; }
    else if (q < 5376) { qb = 5120; qs = 4; }
    else               { qb = 5376; qs = 3; }
    int idx = q - qb;
    int Wq  = 1 << qs;
    float invW = 1.0f / (float)Wq;
    float refx = ((idx & (Wq - 1)) + 0.5f) * invW;
    float refy = ((idx >> qs) + 0.5f) * invW;

    const float* lg = oa + (size_t)bq * 384 + 256 + h * 16;
    float xv = (lane < 16) ? lg[lane] : -1e30f;
    float m = xv;
    #pragma unroll
    for (int o = 8; o; o >>= 1) m = fmaxf(m, __shfl_xor_sync(0xffffffffu, m, o));
    float e = (lane < 16) ? __expf(xv - m) : 0.0f;
    float s = e;
    #pragma unroll
    for (int o = 8; o; o >>= 1) s += __shfl_xor_sync(0xffffffffu, s, o);
    float aw = e / s;

    float offv = oa[(size_t)bq * 384 + h * 32 + lane];

    int group  = lane >> 4;
    int corner = (lane >> 2) & 3;
    int cx = corner & 1;
    int cy = corner >> 1;
    int chunk  = lane & 3;

    const __half* vbase = vh + (size_t)b * LQ_ * 256 + h * HD_ + chunk * 8;

    float acc[8];
    #pragma unroll
    for (int j = 0; j < 8; j++) acc[j] = 0.0f;

    const int dims [4] = {64, 32, 16, 8};
    const int bases[4] = {0, 4096, 5120, 5376};

    #pragma unroll
    for (int l = 0; l < 4; l++) {
        const int Wl = dims[l];
        const int base = bases[l];
        const float Wf = (float)Wl;
        #pragma unroll
        for (int pp = 0; pp < 2; pp++) {
            int pt = l * 4 + pp * 2 + group;
            float ax = __shfl_sync(0xffffffffu, offv, pt * 2 + 0);
            float ay = __shfl_sync(0xffffffffu, offv, pt * 2 + 1);
            float a  = __shfl_sync(0xffffffffu, aw, pt);
            float xf = refx * Wf + ax - 0.5f;
            float yf = refy * Wf + ay - 0.5f;
            float x0f = floorf(xf), y0f = floorf(yf);
            float wx = xf - x0f, wy = yf - y0f;
            int xc = (int)x0f + cx;
            int yc = (int)y0f + cy;
            float wxt = cx ? wx : (1.f - wx);
            float wyt = cy ? wy : (1.f - wy);
            bool valid = (xc >= 0) & (xc < Wl) & (yc >= 0) & (yc < Wl);
            float w = valid ? (a * wxt * wyt) : 0.f;
            // wrap clamp: Wl is pow2; OOB coords wrap to in-bounds addresses, weight = 0
            int xcc = xc & (Wl - 1);
            int ycc = yc & (Wl - 1);

            uint4 d = *(const uint4*)(vbase + (size_t)(base + ycc * Wl + xcc) * 256);
            const __half2* hp = (const __half2*)&d;
            #pragma unroll
            for (int j = 0; j < 4; j++) {
                float2 f = __half22float2(hp[j]);
                acc[2 * j + 0] = fmaf(w, f.x, acc[2 * j + 0]);
                acc[2 * j + 1] = fmaf(w, f.y, acc[2 * j + 1]);
            }
        }
    }

    #pragma unroll
    for (int o = 4; o <= 16; o <<= 1)
        #pragma unroll
        for (int j = 0; j < 8; j++)
            acc[j] += __shfl_xor_sync(0xffffffffu, acc[j], o);

    if (lane < 4) {
        __half2 p0 = __floats2half2_rn(acc[0], acc[1]);
        __half2 p1 = __floats2half2_rn(acc[2], acc[3]);
        __half2 p2 = __floats2half2_rn(acc[4], acc[5]);
        __half2 p3 = __floats2half2_rn(acc[6], acc[7]);
        uint4 pk = {*(uint32_t*)&p0, *(uint32_t*)&p1, *(uint32_t*)&p2, *(uint32_t*)&p3};
        *(uint4*)(out16 + (size_t)bq * 256 + h * HD_ + chunk * 8) = pk;
    }
}

// ---------------- host orchestration ----------------
static void* sym_ptr_raw(const void* sym)
{
    void* p = nullptr;
    cudaGetSymbolAddress(&p, sym);
    return p;
}

extern "C" void kernel_launch(void* const* d_in, const int* in_sizes, int n_in,
                              void* d_out, int out_size)
{
    bool interleaved = (in_sizes[1] == in_sizes[0]);
    const float* srcs[4];
    const float* poss[4];
    for (int l = 0; l < 4; l++) {
        srcs[l] = (const float*)d_in[interleaved ? 2 * l     : l];
        poss[l] = (const float*)d_in[interleaved ? 2 * l + 1 : 4 + l];
    }
    const float* level_embed = (const float*)d_in[8];
    const float* W_off  = (const float*)d_in[9];
    const float* b_off  = (const float*)d_in[10];
    const float* W_attn = (const float*)d_in[11];
    const float* b_attn = (const float*)d_in[12];
    const float* W_v    = (const float*)d_in[13];
    const float* b_v    = (const float*)d_in[14];
    const float* W_o    = (const float*)d_in[15];
    const float* b_o    = (const float*)d_in[16];
    const float* ln1_g  = (const float*)d_in[17];
    const float* ln1_b  = (const float*)d_in[18];
    const float* W_fc1  = (const float*)d_in[19];
    const float* b_fc1  = (const float*)d_in[20];
    const float* W_fc2  = (const float*)d_in[21];
    const float* b_fc2  = (const float*)d_in[22];
    const float* ln2_g  = (const float*)d_in[23];
    const float* ln2_b  = (const float*)d_in[24];

    float*  pos   = (float*) sym_ptr_raw(g_pos);
    float*  out   = (float*) sym_ptr_raw(g_out);
    __half* out16 = (__half*)sym_ptr_raw(g_out16);
    __half* qp16  = (__half*)sym_ptr_raw(g_qpos16);
    float*  oa    = (float*) sym_ptr_raw(g_oa);
    __half* vh    = (__half*)sym_ptr_raw(g_vh);
    __half* def16 = (__half*)sym_ptr_raw(g_def16);
    __half* ffn16 = (__half*)sym_ptr_raw(g_ffn16);
    __half* wvoa  = (__half*)sym_ptr_raw(g_wh_voa);
    __half* wo    = (__half*)sym_ptr_raw(g_wh_o);
    __half* wf1   = (__half*)sym_ptr_raw(g_wh_f1);
    __half* wf2   = (__half*)sym_ptr_raw(g_wh_f2);
    float*  bc    = (float*) sym_ptr_raw(g_bc);

    cudaFuncSetAttribute(tgemm16_kernel<0,1>, cudaFuncAttributeMaxDynamicSharedMemorySize, GEMM_SMEM);
    cudaFuncSetAttribute(tgemm16_kernel<1,2>, cudaFuncAttributeMaxDynamicSharedMemorySize, GEMM_SMEM);
    cudaFuncSetAttribute(tgemm16_ln_kernel, cudaFuncAttributeMaxDynamicSharedMemorySize, LGEMM_SMEM);

    dim3 tb(32, 8);
    flatten_all_kernel<<<dim3(170, D_ / 32, B_), tb>>>(
        srcs[0], srcs[1], srcs[2], srcs[3],
        poss[0], poss[1], poss[2], poss[3],
        level_embed, out, pos, out16, qp16);                               // 1
    wtrans_all_kernel<<<dim3(737, 1, NL_), tb>>>(W_v, W_off, W_attn, W_o, W_fc1, W_fc2,
                                                 b_v, b_off, b_attn,
                                                 wvoa, wo, wf1, wf2, bc);  // 2

    const int MB = MROWS / 128; // 170
    const int LB = MROWS / 64;  // 340
    for (int i = 0; i < NL_; i++) {
        const __half* Wvoa = wvoa  + (size_t)i * 640 * 256;
        const float*  Bc   = bc    + (size_t)i * 640;
        const __half* Wo   = wo    + (size_t)i * 256 * 256;
        const float*  bo   = b_o   + (size_t)i * D_;
        const __half* Wf1  = wf1   + (size_t)i * 1024 * 256;
        const float*  bf1  = b_fc1 + (size_t)i * FF_;
        const __half* Wf2  = wf2   + (size_t)i * 256 * 1024;
        const float*  bf2  = b_fc2 + (size_t)i * D_;

        tgemm16_kernel<0,1><<<dim3(5, MB), 256, GEMM_SMEM>>>(
            out16, qp16, Wvoa, Bc, oa, vh, 640, 256, 2);                   // 3

        deform_kernel<<<MROWS, 256>>>(vh, oa, def16);                      // 4 <- profiled

        tgemm16_ln_kernel<<<LB, 256, LGEMM_SMEM>>>(def16, Wo, bo, out,
            ln1_g + i * D_, ln1_b + i * D_, out, out16, nullptr, nullptr, 256);

        tgemm16_kernel<1,2><<<dim3(8, MB), 256, GEMM_SMEM>>>(
            out16, out16, Wf1, bf1, nullptr, ffn16, 1024, 256, 0);

        if (i == NL_ - 1) {
            tgemm16_ln_kernel<<<LB, 256, LGEMM_SMEM>>>(ffn16, Wf2, bf2, out,
                ln2_g + i * D_, ln2_b + i * D_, (float*)d_out, nullptr, nullptr, nullptr, 1024);
        } else {
            tgemm16_ln_kernel<<<LB, 256, LGEMM_SMEM>>>(ffn16, Wf2, bf2, out,
                ln2_g + i * D_, ln2_b + i * D_, out, out16, pos, qp16, 1024);
        }
    }
}

// round 17
// speedup vs baseline: 1.1420x; 1.0855x over previous
#include <cuda_runtime.h>
#include <cuda_fp16.h>
#include <math.h>
#include <stdint.h>

#define B_  4
#define LQ_ 5440
#define D_  256
#define H_  8
#define HD_ 32
#define FF_ 1024
#define NL_ 6
#define MROWS (B_*LQ_)   // 21760

// ---------------- scratch (device globals; no allocation) ----------------
__device__ float  g_pos  [MROWS*D_];
__device__ float  g_out  [MROWS*D_];
__device__ __half g_out16[MROWS*D_];
__device__ __half g_qpos16[MROWS*D_];
__device__ float  g_oa   [MROWS*384];
__device__ __half g_vh   [MROWS*256];
__device__ __half g_def16[MROWS*D_];
__device__ __half g_ffn16[MROWS*FF_];
__device__ __half g_wh_voa[NL_*640*256];
__device__ __half g_wh_o  [NL_*256*256];
__device__ __half g_wh_f1 [NL_*1024*256];
__device__ __half g_wh_f2 [NL_*256*1024];
__device__ float  g_bc    [NL_*640];

// ---------------- fused flatten ----------------
__global__ void flatten_all_kernel(
    const float* __restrict__ s0, const float* __restrict__ s1,
    const float* __restrict__ s2, const float* __restrict__ s3,
    const float* __restrict__ p0, const float* __restrict__ p1,
    const float* __restrict__ p2, const float* __restrict__ p3,
    const float* __restrict__ lvl_emb,
    float* __restrict__ dsrc, float* __restrict__ dpos,
    __half* __restrict__ dsrc16, __half* __restrict__ dqpos16)
{
    __shared__ float ts[32][33];
    __shared__ float tp[32][33];

    int t = blockIdx.x;
    int level, hwt, HW, base;
    if      (t < 128) { level = 0; hwt = t;       HW = 4096; base = 0;    }
    else if (t < 160) { level = 1; hwt = t - 128; HW = 1024; base = 4096; }
    else if (t < 168) { level = 2; hwt = t - 160; HW = 256;  base = 5120; }
    else              { level = 3; hwt = t - 168; HW = 64;   base = 5376; }

    const float* src = (level == 0) ? s0 : (level == 1) ? s1 : (level == 2) ? s2 : s3;
    const float* pos = (level == 0) ? p0 : (level == 1) ? p1 : (level == 2) ? p2 : p3;

    int b  = blockIdx.z;
    int tx = threadIdx.x, ty = threadIdx.y;
    int hw0 = hwt * 32;
    int d0  = blockIdx.y * 32;

    const float* sp = src + ((size_t)b * D_) * HW;
    const float* pp = pos + ((size_t)b * D_) * HW;
    #pragma unroll
    for (int j = 0; j < 32; j += 8) {
        ts[ty + j][tx] = sp[(size_t)(d0 + ty + j) * HW + hw0 + tx];
        tp[ty + j][tx] = pp[(size_t)(d0 + ty + j) * HW + hw0 + tx];
    }
    __syncthreads();
    float add = lvl_emb[level * D_ + d0 + tx];
    #pragma unroll
    for (int j = 0; j < 32; j += 8) {
        int hw = hw0 + ty + j;
        size_t row = ((size_t)b * LQ_ + base + hw) * D_ + d0 + tx;
        float sv = ts[tx][ty + j];
        float pv = tp[tx][ty + j] + add;
        dsrc[row]    = sv;
        dpos[row]    = pv;
        dsrc16[row]  = __float2half(sv);
        dqpos16[row] = __float2half(sv + pv);
    }
}

// ---------------- fused weight transpose (f32 [K,N] -> f16 [N,K]) + bias ----------
__global__ void wtrans_all_kernel(
    const float* __restrict__ Wv,  const float* __restrict__ Woff,
    const float* __restrict__ Wattn, const float* __restrict__ Wo,
    const float* __restrict__ Wf1, const float* __restrict__ Wf2,
    const float* __restrict__ bv, const float* __restrict__ boff,
    const float* __restrict__ battn,
    __half* __restrict__ wvoa, __half* __restrict__ wo,
    __half* __restrict__ wf1, __half* __restrict__ wf2,
    float* __restrict__ bc)
{
    __shared__ float t[32][33];
    int tl = blockIdx.x, l = blockIdx.z;
    int tid = threadIdx.y * 32 + threadIdx.x;

    if (tl == 736) {
        for (int n = tid; n < 640; n += 256) {
            float v;
            if      (n < 256) v = bv  [l * 256 + n];
            else if (n < 512) v = boff[l * 256 + (n - 256)];
            else              v = battn[l * 128 + (n - 512)];
            bc[l * 640 + n] = v;
        }
        return;
    }

    const float* src; __half* dst; int K, N, idx;
    if      (tl < 64)  { src=Wv   +(size_t)l*65536;  dst=wvoa+(size_t)l*163840;          K=256;  N=256;  idx=tl;       }
    else if (tl < 128) { src=Woff +(size_t)l*65536;  dst=wvoa+(size_t)l*163840+65536;    K=256;  N=256;  idx=tl-64;    }
    else if (tl < 160) { src=Wattn+(size_t)l*32768;  dst=wvoa+(size_t)l*163840+131072;   K=256;  N=128;  idx=tl-128;   }
    else if (tl < 224) { src=Wo   +(size_t)l*65536;  dst=wo  +(size_t)l*65536;           K=256;  N=256;  idx=tl-160;   }
    else if (tl < 480) { src=Wf1  +(size_t)l*262144; dst=wf1 +(size_t)l*262144;          K=256;  N=1024; idx=tl-224;   }
    else               { src=Wf2  +(size_t)l*262144; dst=wf2 +(size_t)l*262144;          K=1024; N=256;  idx=tl-480;   }
    int ntn = N >> 5;
    int n0 = (idx % ntn) * 32;
    int k0 = (idx / ntn) * 32;
    int tx = threadIdx.x, ty = threadIdx.y;
    #pragma unroll
    for (int j = 0; j < 32; j += 8)
        t[ty + j][tx] = src[(size_t)(k0 + ty + j) * N + n0 + tx];
    __syncthreads();
    #pragma unroll
    for (int j = 0; j < 32; j += 8)
        dst[(size_t)(n0 + ty + j) * K + k0 + tx] = __float2half(t[tx][ty + j]);
}

// ---------------- asm helpers ----------------
__device__ __forceinline__ void mma_f16(float* d, const uint32_t* a, const uint32_t* b)
{
    asm volatile("mma.sync.aligned.m16n8k16.row.col.f32.f16.f16.f32 "
        "{%0,%1,%2,%3}, {%4,%5,%6,%7}, {%8,%9}, {%0,%1,%2,%3};"
        : "+f"(d[0]), "+f"(d[1]), "+f"(d[2]), "+f"(d[3])
        : "r"(a[0]), "r"(a[1]), "r"(a[2]), "r"(a[3]), "r"(b[0]), "r"(b[1]));
}
__device__ __forceinline__ void ldsm4(uint32_t* r, uint32_t addr)
{
    asm volatile("ldmatrix.sync.aligned.m8n8.x4.shared.b16 {%0,%1,%2,%3}, [%4];"
        : "=r"(r[0]), "=r"(r[1]), "=r"(r[2]), "=r"(r[3]) : "r"(addr));
}
__device__ __forceinline__ void cpa16(uint32_t dst, const void* src)
{
    asm volatile("cp.async.cg.shared.global [%0], [%1], 16;" :: "r"(dst), "l"(src));
}
#define CP_COMMIT() asm volatile("cp.async.commit_group;" ::: "memory")
#define CP_WAIT2()  asm volatile("cp.async.wait_group 2;" ::: "memory")

// ================= fp16 GEMM A: BM=128 BN=128 BK=32 (VOA, FC1) ==================
#define STG_BYTES 20480
#define GEMM_SMEM (4*STG_BYTES)
template<int DO_RELU, int MODE>
__global__ void __launch_bounds__(256, 2) tgemm16_kernel(
    const __half* __restrict__ A0, const __half* __restrict__ A1,
    const __half* __restrict__ Wt, const float* __restrict__ bias,
    float* __restrict__ C, __half* __restrict__ C16,
    int N, int K, int bn_split)
{
    extern __shared__ char smc[];
    uint32_t smb = (uint32_t)__cvta_generic_to_shared(smc);

    int tid  = threadIdx.x;
    int lane = tid & 31;
    int wrp  = tid >> 5;
    int g    = lane >> 2;
    int tg   = lane & 3;

    int bm = blockIdx.y * 128;
    int bn = blockIdx.x * 128;
    int wm = (wrp >> 2) * 64;
    int wn = (wrp & 3) * 32;

    const __half* A = ((int)blockIdx.x < bn_split) ? A0 : A1;

    int r0l = (tid + 0)   >> 2, c0l = (tid + 0)   & 3;
    int r1l = (tid + 256) >> 2, c1l = (tid + 256) & 3;
    const __half* gA0 = A  + (size_t)(bm + r0l) * K + c0l * 8;
    const __half* gA1 = A  + (size_t)(bm + r1l) * K + c1l * 8;
    const __half* gB0 = Wt + (size_t)(bn + r0l) * K + c0l * 8;
    const __half* gB1 = Wt + (size_t)(bn + r1l) * K + c1l * 8;
    uint32_t dA0 = r0l * 80 + c0l * 16;
    uint32_t dA1 = r1l * 80 + c1l * 16;

    uint32_t a_off = (uint32_t)((lane & 15) * 80 + ((lane & 16) ? 16 : 0));
    uint32_t b_off = (uint32_t)(((lane & 7) + ((lane & 16) ? 8 : 0)) * 80 + ((lane & 8) ? 16 : 0));

    float acc[4][4][4];
    #pragma unroll
    for (int i = 0; i < 4; i++)
        #pragma unroll
        for (int j = 0; j < 4; j++)
            #pragma unroll
            for (int r = 0; r < 4; r++) acc[i][j][r] = 0.0f;

    int NIT = K >> 5;

    #pragma unroll
    for (int s = 0; s < 3; s++) {
        int k0 = s << 5;
        uint32_t sb = smb + s * STG_BYTES;
        cpa16(sb + dA0,         gA0 + k0);
        cpa16(sb + dA1,         gA1 + k0);
        cpa16(sb + 10240 + dA0, gB0 + k0);
        cpa16(sb + 10240 + dA1, gB1 + k0);
        CP_COMMIT();
    }

    for (int it = 0; it < NIT; it++) {
        CP_WAIT2();
        __syncthreads();

        if (it + 3 < NIT) {
            int s = (it + 3) & 3;
            int k0 = (it + 3) << 5;
            uint32_t sb = smb + s * STG_BYTES;
            cpa16(sb + dA0,         gA0 + k0);
            cpa16(sb + dA1,         gA1 + k0);
            cpa16(sb + 10240 + dA0, gB0 + k0);
            cpa16(sb + 10240 + dA1, gB1 + k0);
        }
        CP_COMMIT();

        uint32_t sb = smb + (it & 3) * STG_BYTES;
        uint32_t abase = sb + wm * 80 + a_off;
        uint32_t bbase = sb + 10240 + wn * 80 + b_off;

        #pragma unroll
        for (int ksg = 0; ksg < 2; ksg++) {
            uint32_t a[4][4];
            #pragma unroll
            for (int mt = 0; mt < 4; mt++)
                ldsm4(a[mt], abase + mt * 16 * 80 + ksg * 32);
            uint32_t b[4][2];
            #pragma unroll
            for (int ntp = 0; ntp < 2; ntp++) {
                uint32_t r[4];
                ldsm4(r, bbase + ntp * 16 * 80 + ksg * 32);
                b[2 * ntp + 0][0] = r[0]; b[2 * ntp + 0][1] = r[1];
                b[2 * ntp + 1][0] = r[2]; b[2 * ntp + 1][1] = r[3];
            }
            #pragma unroll
            for (int mt = 0; mt < 4; mt++)
                #pragma unroll
                for (int nt = 0; nt < 4; nt++)
                    mma_f16(acc[mt][nt], a[mt], b[nt]);
        }
    }

    bool v16 = (MODE == 1) && ((int)blockIdx.x < bn_split);
    #pragma unroll
    for (int nt = 0; nt < 4; nt++) {
        int n = bn + wn + nt * 8 + 2 * tg;
        float b0 = bias[n], b1 = bias[n + 1];
        #pragma unroll
        for (int mt = 0; mt < 4; mt++) {
            int m0 = bm + wm + mt * 16 + g;
            float l0 = acc[mt][nt][0] + b0, l1 = acc[mt][nt][1] + b1;
            float h0 = acc[mt][nt][2] + b0, h1 = acc[mt][nt][3] + b1;
            if (DO_RELU) {
                l0 = fmaxf(l0, 0.f); l1 = fmaxf(l1, 0.f);
                h0 = fmaxf(h0, 0.f); h1 = fmaxf(h1, 0.f);
            }
            if (MODE == 1) {
                if (v16) {
                    *(__half2*)(C16 + (size_t)m0 * 256 + n)       = __floats2half2_rn(l0, l1);
                    *(__half2*)(C16 + (size_t)(m0 + 8) * 256 + n) = __floats2half2_rn(h0, h1);
                } else {
                    int nc = n - 256;
                    float2 lo = {l0, l1}, hi = {h0, h1};
                    *(float2*)(C + (size_t)m0 * 384 + nc)       = lo;
                    *(float2*)(C + (size_t)(m0 + 8) * 384 + nc) = hi;
                }
            } else {
                *(__half2*)(C16 + (size_t)m0 * N + n)       = __floats2half2_rn(l0, l1);
                *(__half2*)(C16 + (size_t)(m0 + 8) * N + n) = __floats2half2_rn(h0, h1);
            }
        }
    }
}

// ========== fp16 GEMM B: BM=64 BN=256, LN-fused epilogue (O-proj, FC2) ==========
#define LSTG_BYTES 25600
#define LGEMM_SMEM (4*LSTG_BYTES)
__global__ void __launch_bounds__(256, 2) tgemm16_ln_kernel(
    const __half* __restrict__ A, const __half* __restrict__ Wt,
    const float* __restrict__ bias, const float* __restrict__ X,
    const float* __restrict__ gma, const float* __restrict__ bta,
    float* __restrict__ OUT, __half* __restrict__ OUT16,
    const float* __restrict__ pos, __half* __restrict__ qpos16, int K)
{
    extern __shared__ char smc[];
    uint32_t smb = (uint32_t)__cvta_generic_to_shared(smc);
    __shared__ float red[64][4][2];

    int tid  = threadIdx.x;
    int lane = tid & 31;
    int wrp  = tid >> 5;
    int g    = lane >> 2;
    int tg   = lane & 3;

    int bm = blockIdx.x * 64;
    int wml = (wrp >> 2) * 32;
    int wn  = (wrp & 3) * 64;

    int ra = tid >> 2, ca = tid & 3;
    const __half* gA = A + (size_t)(bm + ra) * K + ca * 8;
    uint32_t dA = ra * 80 + ca * 16;
    const __half* gB[4];
    uint32_t dB[4];
    #pragma unroll
    for (int j = 0; j < 4; j++) {
        int rb = (tid + 256 * j) >> 2, cb = (tid + 256 * j) & 3;
        gB[j] = Wt + (size_t)rb * K + cb * 8;
        dB[j] = 5120 + rb * 80 + cb * 16;
    }

    uint32_t a_off = (uint32_t)((lane & 15) * 80 + ((lane & 16) ? 16 : 0));
    uint32_t b_off = (uint32_t)(((lane & 7) + ((lane & 16) ? 8 : 0)) * 80 + ((lane & 8) ? 16 : 0));

    float acc[2][8][4];
    #pragma unroll
    for (int i = 0; i < 2; i++)
        #pragma unroll
        for (int j = 0; j < 8; j++)
            #pragma unroll
            for (int r = 0; r < 4; r++) acc[i][j][r] = 0.0f;

    int NIT = K >> 5;

    #pragma unroll
    for (int s = 0; s < 3; s++) {
        int k0 = s << 5;
        uint32_t sb = smb + s * LSTG_BYTES;
        cpa16(sb + dA, gA + k0);
        #pragma unroll
        for (int j = 0; j < 4; j++) cpa16(sb + dB[j], gB[j] + k0);
        CP_COMMIT();
    }

    for (int it = 0; it < NIT; it++) {
        CP_WAIT2();
        __syncthreads();

        if (it + 3 < NIT) {
            int s = (it + 3) & 3;
            int k0 = (it + 3) << 5;
            uint32_t sb = smb + s * LSTG_BYTES;
            cpa16(sb + dA, gA + k0);
            #pragma unroll
            for (int j = 0; j < 4; j++) cpa16(sb + dB[j], gB[j] + k0);
        }
        CP_COMMIT();

        uint32_t sb = smb + (it & 3) * LSTG_BYTES;
        uint32_t abase = sb + wml * 80 + a_off;
        uint32_t bbase = sb + 5120 + wn * 80 + b_off;

        #pragma unroll
        for (int ksg = 0; ksg < 2; ksg++) {
            uint32_t a[2][4];
            #pragma unroll
            for (int mt = 0; mt < 2; mt++)
                ldsm4(a[mt], abase + mt * 16 * 80 + ksg * 32);
            uint32_t b[8][2];
            #pragma unroll
            for (int ntp = 0; ntp < 4; ntp++) {
                uint32_t r[4];
                ldsm4(r, bbase + ntp * 16 * 80 + ksg * 32);
                b[2 * ntp + 0][0] = r[0]; b[2 * ntp + 0][1] = r[1];
                b[2 * ntp + 1][0] = r[2]; b[2 * ntp + 1][1] = r[3];
            }
            #pragma unroll
            for (int mt = 0; mt < 2; mt++)
                #pragma unroll
                for (int nt = 0; nt < 8; nt++)
                    mma_f16(acc[mt][nt], a[mt], b[nt]);
        }
    }
    __syncthreads();

    float sum[2][2] = {{0, 0}, {0, 0}};
    float sq [2][2] = {{0, 0}, {0, 0}};
    #pragma unroll
    for (int mt = 0; mt < 2; mt++) {
        #pragma unroll
        for (int nt = 0; nt < 8; nt++) {
            int n = wn + nt * 8 + 2 * tg;
            float b0 = bias[n], b1 = bias[n + 1];
            int mA = bm + wml + mt * 16 + g;
            float2 x0 = *(const float2*)(X + (size_t)mA * 256 + n);
            float2 x1 = *(const float2*)(X + (size_t)(mA + 8) * 256 + n);
            acc[mt][nt][0] += b0 + x0.x;
            acc[mt][nt][1] += b1 + x0.y;
            acc[mt][nt][2] += b0 + x1.x;
            acc[mt][nt][3] += b1 + x1.y;
            sum[mt][0] += acc[mt][nt][0] + acc[mt][nt][1];
            sum[mt][1] += acc[mt][nt][2] + acc[mt][nt][3];
            sq[mt][0]  += acc[mt][nt][0] * acc[mt][nt][0] + acc[mt][nt][1] * acc[mt][nt][1];
            sq[mt][1]  += acc[mt][nt][2] * acc[mt][nt][2] + acc[mt][nt][3] * acc[mt][nt][3];
        }
    }
    #pragma unroll
    for (int mt = 0; mt < 2; mt++)
        #pragma unroll
        for (int rr = 0; rr < 2; rr++) {
            #pragma unroll
            for (int o = 1; o < 4; o <<= 1) {
                sum[mt][rr] += __shfl_xor_sync(0xffffffffu, sum[mt][rr], o);
                sq [mt][rr] += __shfl_xor_sync(0xffffffffu, sq [mt][rr], o);
            }
        }
    int nw = wrp & 3;
    if (tg == 0) {
        #pragma unroll
        for (int mt = 0; mt < 2; mt++)
            #pragma unroll
            for (int rr = 0; rr < 2; rr++) {
                int rl = wml + mt * 16 + g + rr * 8;
                red[rl][nw][0] = sum[mt][rr];
                red[rl][nw][1] = sq[mt][rr];
            }
    }
    __syncthreads();

    #pragma unroll
    for (int mt = 0; mt < 2; mt++) {
        #pragma unroll
        for (int rr = 0; rr < 2; rr++) {
            int rl = wml + mt * 16 + g + rr * 8;
            float s  = red[rl][0][0] + red[rl][1][0] + red[rl][2][0] + red[rl][3][0];
            float s2 = red[rl][0][1] + red[rl][1][1] + red[rl][2][1] + red[rl][3][1];
            float mean = s * (1.0f / 256.0f);
            float var  = s2 * (1.0f / 256.0f) - mean * mean;
            float inv  = rsqrtf(var + 1e-5f);
            int m = bm + rl;
            #pragma unroll
            for (int nt = 0; nt < 8; nt++) {
                int n = wn + nt * 8 + 2 * tg;
                float g0 = gma[n], g1 = gma[n + 1];
                float t0 = bta[n], t1 = bta[n + 1];
                float v0 = acc[mt][nt][2 * rr + 0];
                float v1 = acc[mt][nt][2 * rr + 1];
                float o0 = (v0 - mean) * inv * g0 + t0;
                float o1 = (v1 - mean) * inv * g1 + t1;
                float2 ov = {o0, o1};
                *(float2*)(OUT + (size_t)m * 256 + n) = ov;
                if (OUT16)
                    *(__half2*)(OUT16 + (size_t)m * 256 + n) = __floats2half2_rn(o0, o1);
                if (qpos16) {
                    float2 pv = *(const float2*)(pos + (size_t)m * 256 + n);
                    *(__half2*)(qpos16 + (size_t)m * 256 + n) =
                        __floats2half2_rn(o0 + pv.x, o1 + pv.y);
                }
            }
        }
    }
}

// ---------------- deformable attention: fp16 HFMA2 accumulation ----------------
__global__ void __launch_bounds__(256) deform_kernel(
    const __half* __restrict__ vh,
    const float* __restrict__ oa,
    __half* __restrict__ out16)
{
    int bq   = blockIdx.x;
    int h    = threadIdx.x >> 5;
    int lane = threadIdx.x & 31;
    int b = bq / LQ_;
    int q = bq % LQ_;

    int qb, qs;
    if      (q < 4096) { qb = 0;    qs = 6; }
    else if (q < 5120) { qb = 4096; qs = 5; }
    else if (q < 5376) { qb = 5120; qs = 4; }
    else               { qb = 5376; qs = 3; }
    int idx = q - qb;
    int Wq  = 1 << qs;
    float invW = 1.0f / (float)Wq;
    float refx = ((idx & (Wq - 1)) + 0.5f) * invW;
    float refy = ((idx >> qs) + 0.5f) * invW;

    const float* lg = oa + (size_t)bq * 384 + 256 + h * 16;
    float xv = (lane < 16) ? lg[lane] : -1e30f;
    float m = xv;
    #pragma unroll
    for (int o = 8; o; o >>= 1) m = fmaxf(m, __shfl_xor_sync(0xffffffffu, m, o));
    float e = (lane < 16) ? __expf(xv - m) : 0.0f;
    float s = e;
    #pragma unroll
    for (int o = 8; o; o >>= 1) s += __shfl_xor_sync(0xffffffffu, s, o);
    float aw = e / s;

    float offv = oa[(size_t)bq * 384 + h * 32 + lane];

    int group  = lane >> 4;
    int corner = (lane >> 2) & 3;
    int cx = corner & 1;
    int cy = corner >> 1;
    int chunk  = lane & 3;

    const __half* vbase = vh + (size_t)b * LQ_ * 256 + h * HD_ + chunk * 8;

    __half2 hacc[4];
    #pragma unroll
    for (int j = 0; j < 4; j++) hacc[j] = __half2half2(__float2half(0.0f));

    const int dims [4] = {64, 32, 16, 8};
    const int bases[4] = {0, 4096, 5120, 5376};

    #pragma unroll
    for (int l = 0; l < 4; l++) {
        const int Wl = dims[l];
        const int base = bases[l];
        const float Wf = (float)Wl;
        #pragma unroll
        for (int pp = 0; pp < 2; pp++) {
            int pt = l * 4 + pp * 2 + group;
            float ax = __shfl_sync(0xffffffffu, offv, pt * 2 + 0);
            float ay = __shfl_sync(0xffffffffu, offv, pt * 2 + 1);
            float a  = __shfl_sync(0xffffffffu, aw, pt);
            float xf = refx * Wf + ax - 0.5f;
            float yf = refy * Wf + ay - 0.5f;
            float x0f = floorf(xf), y0f = floorf(yf);
            float wx = xf - x0f, wy = yf - y0f;
            int xc = (int)x0f + cx;
            int yc = (int)y0f + cy;
            float wxt = cx ? wx : (1.f - wx);
            float wyt = cy ? wy : (1.f - wy);
            bool valid = (xc >= 0) & (xc < Wl) & (yc >= 0) & (yc < Wl);
            float w = valid ? (a * wxt * wyt) : 0.f;
            int xcc = xc & (Wl - 1);
            int ycc = yc & (Wl - 1);

            __half2 wh2 = __half2half2(__float2half(w));
            uint4 d = *(const uint4*)(vbase + (size_t)(base + ycc * Wl + xcc) * 256);
            const __half2* hp = (const __half2*)&d;
            #pragma unroll
            for (int j = 0; j < 4; j++)
                hacc[j] = __hfma2(wh2, hp[j], hacc[j]);
        }
    }

    // reduce over corners (bits 2,3) and point parity (bit 4) in fp16
    #pragma unroll
    for (int o = 4; o <= 16; o <<= 1) {
        #pragma unroll
        for (int j = 0; j < 4; j++) {
            uint32_t u = __shfl_xor_sync(0xffffffffu, *(uint32_t*)&hacc[j], o);
            hacc[j] = __hadd2(hacc[j], *(__half2*)&u);
        }
    }

    if (lane < 4) {
        uint4 pk = {*(uint32_t*)&hacc[0], *(uint32_t*)&hacc[1],
                    *(uint32_t*)&hacc[2], *(uint32_t*)&hacc[3]};
        *(uint4*)(out16 + (size_t)bq * 256 + h * HD_ + chunk * 8) = pk;
    }
}

// ---------------- host orchestration ----------------
static void* sym_ptr_raw(const void* sym)
{
    void* p = nullptr;
    cudaGetSymbolAddress(&p, sym);
    return p;
}

extern "C" void kernel_launch(void* const* d_in, const int* in_sizes, int n_in,
                              void* d_out, int out_size)
{
    bool interleaved = (in_sizes[1] == in_sizes[0]);
    const float* srcs[4];
    const float* poss[4];
    for (int l = 0; l < 4; l++) {
        srcs[l] = (const float*)d_in[interleaved ? 2 * l     : l];
        poss[l] = (const float*)d_in[interleaved ? 2 * l + 1 : 4 + l];
    }
    const float* level_embed = (const float*)d_in[8];
    const float* W_off  = (const float*)d_in[9];
    const float* b_off  = (const float*)d_in[10];
    const float* W_attn = (const float*)d_in[11];
    const float* b_attn = (const float*)d_in[12];
    const float* W_v    = (const float*)d_in[13];
    const float* b_v    = (const float*)d_in[14];
    const float* W_o    = (const float*)d_in[15];
    const float* b_o    = (const float*)d_in[16];
    const float* ln1_g  = (const float*)d_in[17];
    const float* ln1_b  = (const float*)d_in[18];
    const float* W_fc1  = (const float*)d_in[19];
    const float* b_fc1  = (const float*)d_in[20];
    const float* W_fc2  = (const float*)d_in[21];
    const float* b_fc2  = (const float*)d_in[22];
    const float* ln2_g  = (const float*)d_in[23];
    const float* ln2_b  = (const float*)d_in[24];

    float*  pos   = (float*) sym_ptr_raw(g_pos);
    float*  out   = (float*) sym_ptr_raw(g_out);
    __half* out16 = (__half*)sym_ptr_raw(g_out16);
    __half* qp16  = (__half*)sym_ptr_raw(g_qpos16);
    float*  oa    = (float*) sym_ptr_raw(g_oa);
    __half* vh    = (__half*)sym_ptr_raw(g_vh);
    __half* def16 = (__half*)sym_ptr_raw(g_def16);
    __half* ffn16 = (__half*)sym_ptr_raw(g_ffn16);
    __half* wvoa  = (__half*)sym_ptr_raw(g_wh_voa);
    __half* wo    = (__half*)sym_ptr_raw(g_wh_o);
    __half* wf1   = (__half*)sym_ptr_raw(g_wh_f1);
    __half* wf2   = (__half*)sym_ptr_raw(g_wh_f2);
    float*  bc    = (float*) sym_ptr_raw(g_bc);

    cudaFuncSetAttribute(tgemm16_kernel<0,1>, cudaFuncAttributeMaxDynamicSharedMemorySize, GEMM_SMEM);
    cudaFuncSetAttribute(tgemm16_kernel<1,2>, cudaFuncAttributeMaxDynamicSharedMemorySize, GEMM_SMEM);
    cudaFuncSetAttribute(tgemm16_ln_kernel, cudaFuncAttributeMaxDynamicSharedMemorySize, LGEMM_SMEM);

    dim3 tb(32, 8);
    flatten_all_kernel<<<dim3(170, D_ / 32, B_), tb>>>(
        srcs[0], srcs[1], srcs[2], srcs[3],
        poss[0], poss[1], poss[2], poss[3],
        level_embed, out, pos, out16, qp16);                               // 1
    wtrans_all_kernel<<<dim3(737, 1, NL_), tb>>>(W_v, W_off, W_attn, W_o, W_fc1, W_fc2,
                                                 b_v, b_off, b_attn,
                                                 wvoa, wo, wf1, wf2, bc);  // 2

    const int MB = MROWS / 128; // 170
    const int LB = MROWS / 64;  // 340
    for (int i = 0; i < NL_; i++) {
        const __half* Wvoa = wvoa  + (size_t)i * 640 * 256;
        const float*  Bc   = bc    + (size_t)i * 640;
        const __half* Wo   = wo    + (size_t)i * 256 * 256;
        const float*  bo   = b_o   + (size_t)i * D_;
        const __half* Wf1  = wf1   + (size_t)i * 1024 * 256;
        const float*  bf1  = b_fc1 + (size_t)i * FF_;
        const __half* Wf2  = wf2   + (size_t)i * 256 * 1024;
        const float*  bf2  = b_fc2 + (size_t)i * D_;

        tgemm16_kernel<0,1><<<dim3(5, MB), 256, GEMM_SMEM>>>(
            out16, qp16, Wvoa, Bc, oa, vh, 640, 256, 2);                   // 3

        deform_kernel<<<MROWS, 256>>>(vh, oa, def16);                      // 4 <- profiled

        tgemm16_ln_kernel<<<LB, 256, LGEMM_SMEM>>>(def16, Wo, bo, out,
            ln1_g + i * D_, ln1_b + i * D_, out, out16, nullptr, nullptr, 256);

        tgemm16_kernel<1,2><<<dim3(8, MB), 256, GEMM_SMEM>>>(
            out16, out16, Wf1, bf1, nullptr, ffn16, 1024, 256, 0);

        if (i == NL_ - 1) {
            tgemm16_ln_kernel<<<LB, 256, LGEMM_SMEM>>>(ffn16, Wf2, bf2, out,
                ln2_g + i * D_, ln2_b + i * D_, (float*)d_out, nullptr, nullptr, nullptr, 1024);
        } else {
            tgemm16_ln_kernel<<<LB, 256, LGEMM_SMEM>>>(ffn16, Wf2, bf2, out,
                ln2_g + i * D_, ln2_b + i * D_, out, out16, pos, qp16, 1024);
        }
    }
}